// round 16
// baseline (speedup 1.0000x reference)
#include <cuda_runtime.h>
#include <cuda_bf16.h>
#include <cstdint>

#define BATCH 32
#define L 1024
#define HD 1024

// ---------------- scratch (static device memory; no allocations) ----------------
static __device__ float g_S[(size_t)BATCH * L * L];
static __device__ char g_aC  [(size_t)BATCH << 22];
static __device__ char g_bC  [(size_t)BATCH << 22];
static __device__ char g_PbC [(size_t)BATCH << 22];
static __device__ char g_PaTC[(size_t)BATCH << 22];
static __device__ float g_rmax[BATCH * L];
static __device__ float g_rinv[BATCH * L];
static __device__ float g_cmax[BATCH * L];
static __device__ float g_cinv[BATCH * L];
static __device__ int   g_idxa[BATCH * L];
static __device__ int   g_idxb[BATCH * L];
static __device__ int   g_na[BATCH];
static __device__ int   g_nb[BATCH];
static __device__ float g_amean[BATCH * HD];
static __device__ float g_bmean[BATCH * HD];
static __device__ float g_cpm[8 * BATCH * L];
static __device__ float g_cpl[8 * BATCH * L];
static __device__ float g_rpm[8 * BATCH * L];
static __device__ float g_rpl[8 * BATCH * L];
static __device__ float g_mp[8 * 2 * BATCH * HD];

// ================= helpers =================
__device__ __forceinline__ uint32_t smem_u32(const void* p) {
    uint32_t a;
    asm("{ .reg .u64 t; cvta.to.shared.u64 t, %1; cvt.u32.u64 %0, t; }" : "=r"(a) : "l"(p));
    return a;
}
__device__ __forceinline__ void ldm_x4(uint32_t* r, uint32_t addr) {
    asm volatile("ldmatrix.sync.aligned.m8n8.x4.shared.b16 {%0,%1,%2,%3}, [%4];"
        : "=r"(r[0]), "=r"(r[1]), "=r"(r[2]), "=r"(r[3]) : "r"(addr));
}
__device__ __forceinline__ void ldm_x4_t(uint32_t* r, uint32_t addr) {
    asm volatile("ldmatrix.sync.aligned.m8n8.x4.trans.shared.b16 {%0,%1,%2,%3}, [%4];"
        : "=r"(r[0]), "=r"(r[1]), "=r"(r[2]), "=r"(r[3]) : "r"(addr));
}
__device__ __forceinline__ void mma16816(float* c, const uint32_t* a, const uint32_t* b) {
    asm volatile("mma.sync.aligned.m16n8k16.row.col.f32.bf16.bf16.f32 "
        "{%0,%1,%2,%3}, {%4,%5,%6,%7}, {%8,%9}, {%0,%1,%2,%3};"
        : "+f"(c[0]), "+f"(c[1]), "+f"(c[2]), "+f"(c[3])
        : "r"(a[0]), "r"(a[1]), "r"(a[2]), "r"(a[3]), "r"(b[0]), "r"(b[1]));
}
__device__ __forceinline__ uint32_t cvt_bf2(float y_hi, float x_lo) {
    uint32_t r;
    asm("cvt.rn.bf16x2.f32 %0, %1, %2;" : "=r"(r) : "f"(y_hi), "f"(x_lo));
    return r;
}
__device__ __forceinline__ void split2(float x, float y, uint32_t& h, uint32_t& l) {
    h = cvt_bf2(y, x);
    float xh = __uint_as_float(h << 16);
    float yh = __uint_as_float(h & 0xffff0000u);
    l = cvt_bf2(y - yh, x - xh);
}
__device__ __forceinline__ uint4 pack8(const float* v, bool lo) {
    uint4 w;
    uint32_t h, l;
    split2(v[0], v[1], h, l); w.x = lo ? l : h;
    split2(v[2], v[3], h, l); w.y = lo ? l : h;
    split2(v[4], v[5], h, l); w.z = lo ? l : h;
    split2(v[6], v[7], h, l); w.w = lo ? l : h;
    return w;
}
__device__ __forceinline__ void cpa16(uint32_t dst, const void* src) {
    asm volatile("cp.async.cg.shared.global [%0], [%1], 16;" :: "r"(dst), "l"(src));
}
#define CPA_COMMIT() asm volatile("cp.async.commit_group;" ::: "memory")
#define CPA_WAIT1()  asm volatile("cp.async.wait_group 1;" ::: "memory")

// ================= unified bf16 GEMM: out = A @ B^T over pre-converted tiles =====
// EPI==0: grid z = 16 per chunk, batch = zofs + blockIdx.z
// EPI==1: grid z = 32 per chunk: z<16 -> set1 batch zofs+z, z>=16 -> set2 batch zofs+z-16
template <int EPI, int BTRANS>
__global__ __launch_bounds__(256) void gemm_bf(
    const char* __restrict__ A1, const char* __restrict__ B1, float* __restrict__ o1,
    const int* __restrict__ cntM1, const int* __restrict__ cntN1, const int* __restrict__ idxM1,
    const char* __restrict__ A2, const char* __restrict__ B2, float* __restrict__ o2,
    const int* __restrict__ cntM2, const int* __restrict__ cntN2, const int* __restrict__ idxM2,
    const float* __restrict__ temp_ptr, int zofs)
{
    extern __shared__ char sm[];
    const int tid = threadIdx.x;
    int bz;
    bool second = false;
    if (EPI == 1) {
        second = (blockIdx.z >= 16);
        bz = zofs + (blockIdx.z & 15);
    } else {
        bz = zofs + blockIdx.z;
    }
    const char* Abuf = second ? A2 : A1;
    const char* Bbuf = second ? B2 : B1;
    float* out       = second ? o2 : o1;
    const int* cntM  = second ? cntM2 : cntM1;
    const int* cntN  = second ? cntN2 : cntN1;
    const int* idxM  = second ? idxM2 : idxM1;

    const int cm = cntM[bz];
    const int mc = (cm + 127) & ~127;
    const int rowC = blockIdx.y * 128;
    if (rowC >= mc) return;
    const int colC = blockIdx.x * 128;
    int nstg, nb = 0;
    if (EPI == 0) {
        nb = cntN[bz];
        const int nbc = (nb + 127) & ~127;
        if (colC >= nbc) return;
        nstg = 32;
    } else {
        nstg = (cntN[bz] + 31) >> 5;
    }

    const char* gA = Abuf + ((size_t)bz << 22);
    const char* gB = Bbuf + ((size_t)bz << 22);

    const int lr = tid >> 1;
    const int cb = (tid & 1) * 64;
    const int rB = tid >> 3;
    const int oB = (tid & 7) * 64;
    const int ks0 = colC >> 5;
    const uint32_t smb = smem_u32(sm);

    #define ISSUE_STAGE(s) do { \
        const uint32_t _st = smb + ((s) % 3) * 32768; \
        const uint32_t _dA = _st + lr * 128 + cb; \
        const char* _pA = gA + (((size_t)(rowC + lr) * 32 + (s)) << 7) + cb; \
        cpa16(_dA,          _pA);      cpa16(_dA + 16,         _pA + 16); \
        cpa16(_dA + 32,     _pA + 32); cpa16(_dA + 48,         _pA + 48); \
        if (BTRANS) { \
            const uint32_t _dB = _st + 16384 + rB * 512 + oB; \
            const char* _pB = gB + (((size_t)((s) * 32 + rB) * 32 + ks0) << 7) + oB; \
            cpa16(_dB,      _pB);      cpa16(_dB + 16,     _pB + 16); \
            cpa16(_dB + 32, _pB + 32); cpa16(_dB + 48,     _pB + 48); \
        } else { \
            const uint32_t _dB = _st + 16384 + lr * 128 + cb; \
            const char* _pB = gB + (((size_t)(colC + lr) * 32 + (s)) << 7) + cb; \
            cpa16(_dB,      _pB);      cpa16(_dB + 16,     _pB + 16); \
            cpa16(_dB + 32, _pB + 32); cpa16(_dB + 48,     _pB + 48); \
        } \
    } while (0)

    float acc[2][8][4];
    #pragma unroll
    for (int i = 0; i < 2; i++)
        #pragma unroll
        for (int j = 0; j < 8; j++)
            #pragma unroll
            for (int k = 0; k < 4; k++) acc[i][j][k] = 0.f;

    const int wid = tid >> 5;
    const int l   = tid & 31;
    const int m0 = (wid & 3) * 32;
    const int n0 = (wid >> 2) * 64;
    const int lrA = l & 15;
    const int lcA = l >> 4;
    const int lrB = (l & 7) + ((l & 16) >> 1);
    const int lcB = (l >> 3) & 1;
    const int jof = (l & 7) + ((l & 8) ? 8 : 0);
    const int nof = (l & 16) ? 8 : 0;

    ISSUE_STAGE(0); CPA_COMMIT();
    if (nstg > 1) ISSUE_STAGE(1);
    CPA_COMMIT();

    for (int s = 0; s < nstg; ++s) {
        CPA_WAIT1();
        __syncthreads();
        if (s + 2 < nstg) ISSUE_STAGE(s + 2);
        CPA_COMMIT();

        const uint32_t sAb = smb + (s % 3) * 32768;
        const uint32_t sBb = sAb + 16384;
        #pragma unroll
        for (int kc = 0; kc < 4; kc += 2) {
            uint32_t a_hi[2][4], a_lo[2][4];
            #pragma unroll
            for (int mi = 0; mi < 2; ++mi) {
                const int r = m0 + mi * 16 + lrA;
                const int rx = r & 7;
                ldm_x4(a_hi[mi], sAb + r * 128 + (((kc     + lcA) ^ rx) * 16));
                ldm_x4(a_lo[mi], sAb + r * 128 + (((kc + 4 + lcA) ^ rx) * 16));
            }
            #pragma unroll
            for (int nh = 0; nh < 2; ++nh) {
                uint32_t b_hi[2][4], b_lo[2][4];
                #pragma unroll
                for (int nt = 0; nt < 2; ++nt) {
                    if (BTRANS) {
                        const int jrow = (kc >> 1) * 16 + jof;
                        const int nloc = n0 + nh * 32 + nt * 16 + nof;
                        const int slab = nloc >> 5;
                        const int ch   = (nloc >> 3) & 3;
                        const uint32_t base = sBb + jrow * 512 + slab * 128;
                        const int rx = jrow & 7;
                        ldm_x4_t(b_hi[nt], base + (((ch    ) ^ rx) * 16));
                        ldm_x4_t(b_lo[nt], base + (((ch + 4) ^ rx) * 16));
                    } else {
                        const int r = n0 + nh * 32 + nt * 16 + lrB;
                        const int rx = r & 7;
                        ldm_x4(b_hi[nt], sBb + r * 128 + (((kc     + lcB) ^ rx) * 16));
                        ldm_x4(b_lo[nt], sBb + r * 128 + (((kc + 4 + lcB) ^ rx) * 16));
                    }
                }
                #pragma unroll
                for (int prod = 0; prod < 3; ++prod)
                    #pragma unroll
                    for (int mi = 0; mi < 2; ++mi)
                        #pragma unroll
                        for (int nt = 0; nt < 2; ++nt)
                            #pragma unroll
                            for (int p = 0; p < 2; ++p) {
                                const int j = nh * 4 + nt * 2 + p;
                                mma16816(acc[mi][j],
                                         (prod == 2) ? a_lo[mi] : a_hi[mi],
                                         (prod == 1) ? &b_lo[nt][p * 2] : &b_hi[nt][p * 2]);
                            }
            }
        }
    }
    __syncthreads();

    float* eb = (float*)sm;
    #pragma unroll
    for (int mi = 0; mi < 2; ++mi)
        #pragma unroll
        for (int j = 0; j < 8; ++j) {
            const int r0 = m0 + mi * 16 + (l >> 2);
            const int col = n0 + j * 8 + (l & 3) * 2;
            const int ch = col >> 2, fo = col & 3;
            *(float2*)(eb + r0 * 128 + (ch ^ (r0 & 7)) * 4 + fo) =
                make_float2(acc[mi][j][0], acc[mi][j][1]);
            const int r1 = r0 + 8;
            *(float2*)(eb + r1 * 128 + (ch ^ (r1 & 7)) * 4 + fo) =
                make_float2(acc[mi][j][2], acc[mi][j][3]);
        }
    __syncthreads();

    if (EPI == 0) {
        float* Cb = g_S + ((size_t)bz << 20) + (size_t)rowC * 1024 + colC;
        const float temp = *temp_ptr;
        const int c = tid & 31;
        #pragma unroll
        for (int p = 0; p < 16; ++p) {
            const int row = p * 8 + wid;
            float4 v = *(float4*)(eb + row * 128 + ((c ^ (row & 7)) * 4));
            const bool rv = (rowC + row) < cm;
            const int cbi = colC + c * 4;
            v.x = (rv && cbi + 0 < nb) ? v.x * temp : -10000.0f;
            v.y = (rv && cbi + 1 < nb) ? v.y * temp : -10000.0f;
            v.z = (rv && cbi + 2 < nb) ? v.z * temp : -10000.0f;
            v.w = (rv && cbi + 3 < nb) ? v.w * temp : -10000.0f;
            *(float4*)(Cb + (size_t)row * 1024 + c * 4) = v;
            *(float4*)(eb + row * 128 + ((c ^ (row & 7)) * 4)) = v;
            float m4 = fmaxf(fmaxf(v.x, v.y), fmaxf(v.z, v.w));
            #pragma unroll
            for (int off = 16; off > 0; off >>= 1)
                m4 = fmaxf(m4, __shfl_xor_sync(0xffffffffu, m4, off));
            float e = expf(v.x - m4) + expf(v.y - m4) + expf(v.z - m4) + expf(v.w - m4);
            #pragma unroll
            for (int off = 16; off > 0; off >>= 1)
                e += __shfl_xor_sync(0xffffffffu, e, off);
            if (c == 0) {
                g_rpm[(blockIdx.x * 32 + bz) * 1024 + rowC + row] = m4;
                g_rpl[(blockIdx.x * 32 + bz) * 1024 + rowC + row] = e;
            }
        }
        __syncthreads();
        float* cm2 = (float*)(sm + 65536);
        float* cl2 = cm2 + 128;
        const int col = tid & 127;
        const int half = tid >> 7;
        float m = -1e30f;
        #pragma unroll 4
        for (int r = half * 64; r < half * 64 + 64; ++r)
            m = fmaxf(m, eb[r * 128 + (((col >> 2) ^ (r & 7)) * 4) + (col & 3)]);
        float lsum = 0.f;
        #pragma unroll 4
        for (int r = half * 64; r < half * 64 + 64; ++r)
            lsum += expf(eb[r * 128 + (((col >> 2) ^ (r & 7)) * 4) + (col & 3)] - m);
        if (half == 1) { cm2[col] = m; cl2[col] = lsum; }
        __syncthreads();
        if (half == 0) {
            float pm = cm2[col], pl = cl2[col];
            float nm = fmaxf(m, pm);
            lsum = lsum * expf(m - nm) + pl * expf(pm - nm);
            g_cpm[(blockIdx.y * 32 + bz) * 1024 + colC + col] = nm;
            g_cpl[(blockIdx.y * 32 + bz) * 1024 + colC + col] = lsum;
        }
    } else {
        const int* im = idxM + bz * 1024;
        float* Ob = out + ((size_t)bz << 20);
        #pragma unroll
        for (int p = 0; p < 16; ++p) {
            const int idx = p * 256 + tid;
            const int row = idx >> 5;
            const int c   = idx & 31;
            const int gi = rowC + row;
            if (gi < cm) {
                float4 v = *(float4*)(eb + row * 128 + ((c ^ (row & 7)) * 4));
                *(float4*)(Ob + (size_t)im[gi] * 1024 + colC + c * 4) = v;
            }
        }
    }
    #undef ISSUE_STAGE
}

// ---------------- mask scan: per-batch valid index lists ----------------
__global__ __launch_bounds__(256) void mask_scan(const int* __restrict__ ma,
                                                 const int* __restrict__ mb)
{
    const int b = blockIdx.x;
    const int which = blockIdx.y;
    const int* m = (which ? mb : ma) + b * 1024;
    int* idx = (which ? g_idxb : g_idxa) + b * 1024;
    const int tid = threadIdx.x;
    int4 v = ((const int4*)m)[tid];
    const int c0 = (v.x != 0), c1 = (v.y != 0), c2 = (v.z != 0), c3 = (v.w != 0);
    int s0 = c0 + c1 + c2 + c3;
    __shared__ int ps[256];
    ps[tid] = s0; __syncthreads();
    for (int off = 1; off < 256; off <<= 1) {
        int t = (tid >= off) ? ps[tid - off] : 0;
        __syncthreads();
        ps[tid] += t;
        __syncthreads();
    }
    int p = ps[tid] - s0;
    if (c0) idx[p++] = tid * 4 + 0;
    if (c1) idx[p++] = tid * 4 + 1;
    if (c2) idx[p++] = tid * 4 + 2;
    if (c3) idx[p++] = tid * 4 + 3;
    if (tid == 255) (which ? g_nb : g_na)[b] = ps[255];
}

// ------- conv_km: gathered rows of a/b -> bf16 hi|lo pre-swizzled K-major -------
// chunked: grid y = 32; batch = zofs + (by & 15); which = by >> 4 (0=a, 1=b)
__global__ __launch_bounds__(256) void conv_km(const float* __restrict__ a,
                                               const float* __restrict__ bsrc, int zofs)
{
    const int by = blockIdx.y;
    const int bi = zofs + (by & 15);
    const bool isb = (by >= 16);
    const float* in = (isb ? bsrc : a) + ((size_t)bi << 20);
    char* out = (isb ? g_bC : g_aC) + ((size_t)bi << 22);
    const int* idx = (isb ? g_idxb : g_idxa) + bi * 1024;
    const int cnt = (isb ? g_nb : g_na)[bi];
    const int nc = (cnt + 127) & ~127;
    const int lin = blockIdx.x * 256 + threadIdx.x;
    const int row = lin >> 5;
    if (row >= nc) return;
    char* dst = out + (size_t)lin * 128;
    const int rx = row & 7;
    if (row < cnt) {
        const int ks = lin & 31;
        const float4* src = (const float4*)(in + (size_t)idx[row] * 1024 + ks * 32);
        #pragma unroll
        for (int c = 0; c < 4; ++c) {
            float4 u = src[2 * c], v = src[2 * c + 1];
            float f[8] = {u.x, u.y, u.z, u.w, v.x, v.y, v.z, v.w};
            *(uint4*)(dst + (((c    ) ^ rx) * 16)) = pack8(f, false);
            *(uint4*)(dst + (((c + 4) ^ rx) * 16)) = pack8(f, true);
        }
    } else {
        #pragma unroll
        for (int pc = 0; pc < 8; ++pc)
            *(uint4*)(dst + pc * 16) = make_uint4(0, 0, 0, 0);
    }
}

// ---------------- column means (partials + combine, deterministic) ----------------
__global__ __launch_bounds__(256) void means_part(const float* __restrict__ a,
                                                  const float* __restrict__ bsrc)
{
    const int z = blockIdx.z;
    const float* src = (z < 32 ? a : bsrc) + ((size_t)(z & 31) << 20);
    const int h = blockIdx.x * 256 + threadIdx.x;
    const int s0 = blockIdx.y * 128;
    float sum = 0.f;
    #pragma unroll 4
    for (int s = 0; s < 128; ++s)
        sum += src[(size_t)(s0 + s) * 1024 + h];
    g_mp[((size_t)blockIdx.y * 64 + z) * 1024 + h] = sum;
}
__global__ __launch_bounds__(256) void means_comb()
{
    const int z = blockIdx.y;
    const int h = blockIdx.x * 256 + threadIdx.x;
    float sum = 0.f;
    #pragma unroll
    for (int q = 0; q < 8; ++q)
        sum += g_mp[((size_t)(q * 64 + z) << 10) + h];
    float* dst = (z < 32 ? g_amean : g_bmean) + (z & 31) * 1024;
    dst[h] = sum;
}

// ---------------- merged combine kernel for fused softmax partials ----------------
__global__ __launch_bounds__(256) void stats_comb()
{
    const int b = blockIdx.y;
    const int i = blockIdx.x * 256 + threadIdx.x;
    const int which = blockIdx.z;
    const int qn = ((which ? g_na[b] : g_nb[b]) + 127) >> 7;
    const float* pm_arr = which ? g_cpm : g_rpm;
    const float* pl_arr = which ? g_cpl : g_rpl;
    float m = -1e30f, lsum = 0.f;
    for (int q = 0; q < qn; ++q) {
        float pm = pm_arr[(q * 32 + b) * 1024 + i];
        float pl = pl_arr[(q * 32 + b) * 1024 + i];
        float nm = fmaxf(m, pm);
        lsum = lsum * expf(m - nm) + pl * expf(pm - nm);
        m = nm;
    }
    if (which) {
        g_cmax[b * 1024 + i] = m;
        g_cinv[b * 1024 + i] = 1.0f / lsum;
    } else {
        g_rmax[b * 1024 + i] = m;
        g_rinv[b * 1024 + i] = 1.0f / lsum;
    }
}

// ------- probabilities (chunked): batch = zofs + blockIdx.z -------
__global__ __launch_bounds__(256) void probs_c(int zofs)
{
    const int b  = zofs + blockIdx.z;
    const int nac = (g_na[b] + 127) & ~127;
    const int nbc = (g_nb[b] + 127) & ~127;
    const int t0 = blockIdx.x * 32;
    const int s0 = blockIdx.y * 32;
    if (s0 >= nac || t0 >= nbc) return;
    const int tx = threadIdx.x & 31;
    const int ty = threadIdx.x >> 5;
    __shared__ float pb[32][33];
    __shared__ float pa[32][33];
    const float* Sb = g_S + ((size_t)b << 20);
    const float cm = g_cmax[b * 1024 + t0 + tx];
    const float ci = g_cinv[b * 1024 + t0 + tx];
    #pragma unroll
    for (int r = 0; r < 4; r++) {
        const int s = s0 + ty + r * 8;
        float x = Sb[(size_t)s * 1024 + t0 + tx];
        pb[ty + r * 8][tx] = expf(x - g_rmax[b * 1024 + s]) * g_rinv[b * 1024 + s];
        pa[tx][ty + r * 8] = expf(x - cm) * ci;
    }
    __syncthreads();
    const int row = threadIdx.x >> 3;
    const int c   = threadIdx.x & 7;
    const bool lo = (c >= 4);
    {
        const int s = s0 + row;
        uint4 w = pack8(&pb[row][(c & 3) * 8], lo);
        *(uint4*)(g_PbC + ((size_t)b << 22) + (((size_t)s * 32 + (t0 >> 5)) << 7)
                  + ((c ^ (s & 7)) * 16)) = w;
    }
    {
        const int t = t0 + row;
        uint4 w = pack8(&pa[row][(c & 3) * 8], lo);
        *(uint4*)(g_PaTC + ((size_t)b << 22) + (((size_t)t * 32 + (s0 >> 5)) << 7)
                  + ((c ^ (t & 7)) * 16)) = w;
    }
}

// ------- fill invalid output rows with mean of the opposite tensor ---------
__global__ __launch_bounds__(256) void fill_invalid(const int* __restrict__ mask,
                                                    const float* __restrict__ meansum,
                                                    float* __restrict__ out)
{
    const int b = blockIdx.y;
    const int s = blockIdx.x;
    if (mask[b * 1024 + s]) return;
    const float4 v = ((const float4*)(meansum + b * 1024))[threadIdx.x];
    const float inv = 1.0f / 1024.0f;
    ((float4*)(out + ((size_t)b << 20) + (size_t)s * 1024))[threadIdx.x] =
        make_float4(v.x * inv, v.y * inv, v.z * inv, v.w * inv);
}

// ---------------- launch: batch-chunk pipelined two-stream schedule --------------
extern "C" void kernel_launch(void* const* d_in, const int* in_sizes, int n_in,
                              void* d_out, int out_size)
{
    const float* a    = (const float*)d_in[0];
    const float* b    = (const float*)d_in[1];
    const int*   ma   = (const int*)d_in[2];
    const int*   mb   = (const int*)d_in[3];
    const float* temp = (const float*)d_in[4];

    float* fa = (float*)d_out;
    float* fb = fa + (size_t)BATCH * L * HD;

    float* pS;   cudaGetSymbolAddress((void**)&pS,   g_S);
    char* paC;   cudaGetSymbolAddress((void**)&paC,  g_aC);
    char* pbC;   cudaGetSymbolAddress((void**)&pbC,  g_bC);
    char* pPbC;  cudaGetSymbolAddress((void**)&pPbC, g_PbC);
    char* pPaTC; cudaGetSymbolAddress((void**)&pPaTC, g_PaTC);
    float* pam;  cudaGetSymbolAddress((void**)&pam,  g_amean);
    float* pbm;  cudaGetSymbolAddress((void**)&pbm,  g_bmean);
    int* pna;    cudaGetSymbolAddress((void**)&pna,  g_na);
    int* pnb;    cudaGetSymbolAddress((void**)&pnb,  g_nb);
    int* pia;    cudaGetSymbolAddress((void**)&pia,  g_idxa);
    int* pib;    cudaGetSymbolAddress((void**)&pib,  g_idxb);

    static cudaStream_t s2 = nullptr;
    static cudaEvent_t evM = nullptr, evC1 = nullptr, evS = nullptr, evP1 = nullptr;
    static bool inited = false;
    if (!inited) {
        cudaStreamCreateWithFlags(&s2, cudaStreamNonBlocking);
        cudaEventCreateWithFlags(&evM,  cudaEventDisableTiming);
        cudaEventCreateWithFlags(&evC1, cudaEventDisableTiming);
        cudaEventCreateWithFlags(&evS,  cudaEventDisableTiming);
        cudaEventCreateWithFlags(&evP1, cudaEventDisableTiming);
        const int SMEM = 98304;
        cudaFuncSetAttribute(gemm_bf<0,0>, cudaFuncAttributeMaxDynamicSharedMemorySize, SMEM);
        cudaFuncSetAttribute(gemm_bf<1,1>, cudaFuncAttributeMaxDynamicSharedMemorySize, SMEM);
        inited = true;
    }
    const int SMEM = 98304;

    dim3 blk(256);

    // ---- main: mask scan, then conv chunk 0 ----
    mask_scan<<<dim3(32, 2), blk>>>(ma, mb);
    cudaEventRecord(evM, 0);
    conv_km<<<dim3(128, 32), blk>>>(a, b, 0);

    // ---- s2: conv chunk 1 (overlaps scores GEMM c0), then means/fill chain ----
    cudaStreamWaitEvent(s2, evM, 0);
    conv_km<<<dim3(128, 32), blk, 0, s2>>>(a, b, 16);
    cudaEventRecord(evC1, s2);
    means_part<<<dim3(4, 8, 64), blk, 0, s2>>>(a, b);
    means_comb<<<dim3(4, 64), blk, 0, s2>>>();
    fill_invalid<<<dim3(1024, 32), blk, 0, s2>>>(ma, pbm, fa);
    fill_invalid<<<dim3(1024, 32), blk, 0, s2>>>(mb, pam, fb);

    // ---- main: scores GEMM chunk 0, then (after conv c1) chunk 1 ----
    gemm_bf<0,0><<<dim3(8, 8, 16), blk, SMEM>>>(
        paC, pbC, pS, pna, pnb, nullptr,
        nullptr, nullptr, nullptr, nullptr, nullptr, nullptr, temp, 0);
    cudaStreamWaitEvent(0, evC1, 0);
    gemm_bf<0,0><<<dim3(8, 8, 16), blk, SMEM>>>(
        paC, pbC, pS, pna, pnb, nullptr,
        nullptr, nullptr, nullptr, nullptr, nullptr, nullptr, temp, 16);

    // ---- stats combine (all batches), then probs chunk 0 on main ----
    stats_comb<<<dim3(4, 32, 2), blk>>>();
    cudaEventRecord(evS, 0);
    probs_c<<<dim3(32, 32, 16), blk>>>(0);

    // ---- s2: probs chunk 1 (overlaps feature GEMM c0) ----
    cudaStreamWaitEvent(s2, evS, 0);
    probs_c<<<dim3(32, 32, 16), blk, 0, s2>>>(16);
    cudaEventRecord(evP1, s2);

    // ---- main: feature GEMM chunk 0, then (after probs c1) chunk 1 ----
    gemm_bf<1,1><<<dim3(8, 8, 32), blk, SMEM>>>(
        pPbC, pbC, fa, pna, pnb, pia,
        pPaTC, paC, fb, pnb, pna, pib, nullptr, 0);
    cudaStreamWaitEvent(0, evP1, 0);
    gemm_bf<1,1><<<dim3(8, 8, 32), blk, SMEM>>>(
        pPbC, pbC, fa, pna, pnb, pia,
        pPaTC, paC, fb, pnb, pna, pib, nullptr, 16);
}

// round 17
// speedup vs baseline: 1.1061x; 1.1061x over previous
#include <cuda_runtime.h>
#include <cuda_bf16.h>
#include <cstdint>

#define BATCH 32
#define L 1024
#define HD 1024

// ---------------- scratch (static device memory; no allocations) ----------------
static __device__ float g_S[(size_t)BATCH * L * L];
static __device__ char g_aC  [(size_t)BATCH << 22];
static __device__ char g_bC  [(size_t)BATCH << 22];
static __device__ char g_PbC [(size_t)BATCH << 22];
static __device__ char g_PaTC[(size_t)BATCH << 22];
static __device__ float g_rmax[BATCH * L];
static __device__ float g_rinv[BATCH * L];
static __device__ float g_cmax[BATCH * L];
static __device__ float g_cinv[BATCH * L];
static __device__ int   g_idxa[BATCH * L];
static __device__ int   g_idxb[BATCH * L];
static __device__ int   g_na[BATCH];
static __device__ int   g_nb[BATCH];
static __device__ float g_amean[BATCH * HD];
static __device__ float g_bmean[BATCH * HD];
static __device__ float g_cpm[8 * BATCH * L];
static __device__ float g_cpl[8 * BATCH * L];
static __device__ float g_rpm[8 * BATCH * L];
static __device__ float g_rpl[8 * BATCH * L];
static __device__ float g_mp[8 * 2 * BATCH * HD];

// ================= helpers =================
__device__ __forceinline__ uint32_t smem_u32(const void* p) {
    uint32_t a;
    asm("{ .reg .u64 t; cvta.to.shared.u64 t, %1; cvt.u32.u64 %0, t; }" : "=r"(a) : "l"(p));
    return a;
}
__device__ __forceinline__ void ldm_x4(uint32_t* r, uint32_t addr) {
    asm volatile("ldmatrix.sync.aligned.m8n8.x4.shared.b16 {%0,%1,%2,%3}, [%4];"
        : "=r"(r[0]), "=r"(r[1]), "=r"(r[2]), "=r"(r[3]) : "r"(addr));
}
__device__ __forceinline__ void ldm_x4_t(uint32_t* r, uint32_t addr) {
    asm volatile("ldmatrix.sync.aligned.m8n8.x4.trans.shared.b16 {%0,%1,%2,%3}, [%4];"
        : "=r"(r[0]), "=r"(r[1]), "=r"(r[2]), "=r"(r[3]) : "r"(addr));
}
__device__ __forceinline__ void mma16816(float* c, const uint32_t* a, const uint32_t* b) {
    asm volatile("mma.sync.aligned.m16n8k16.row.col.f32.bf16.bf16.f32 "
        "{%0,%1,%2,%3}, {%4,%5,%6,%7}, {%8,%9}, {%0,%1,%2,%3};"
        : "+f"(c[0]), "+f"(c[1]), "+f"(c[2]), "+f"(c[3])
        : "r"(a[0]), "r"(a[1]), "r"(a[2]), "r"(a[3]), "r"(b[0]), "r"(b[1]));
}
// packed convert: {lo = bf16(x), hi = bf16(y)} in one instruction
__device__ __forceinline__ uint32_t cvt_bf2(float y_hi, float x_lo) {
    uint32_t r;
    asm("cvt.rn.bf16x2.f32 %0, %1, %2;" : "=r"(r) : "f"(y_hi), "f"(x_lo));
    return r;
}
// split 2 floats into packed bf16 hi pair + lo-residual pair (packed cvts)
__device__ __forceinline__ void split2(float x, float y, uint32_t& h, uint32_t& l) {
    h = cvt_bf2(y, x);
    float xh = __uint_as_float(h << 16);
    float yh = __uint_as_float(h & 0xffff0000u);
    l = cvt_bf2(y - yh, x - xh);
}
__device__ __forceinline__ uint4 pack8(const float* v, bool lo) {
    uint4 w;
    uint32_t h, l;
    split2(v[0], v[1], h, l); w.x = lo ? l : h;
    split2(v[2], v[3], h, l); w.y = lo ? l : h;
    split2(v[4], v[5], h, l); w.z = lo ? l : h;
    split2(v[6], v[7], h, l); w.w = lo ? l : h;
    return w;
}
__device__ __forceinline__ void cpa16(uint32_t dst, const void* src) {
    asm volatile("cp.async.cg.shared.global [%0], [%1], 16;" :: "r"(dst), "l"(src));
}
#define CPA_COMMIT() asm volatile("cp.async.commit_group;" ::: "memory")
#define CPA_WAIT1()  asm volatile("cp.async.wait_group 1;" ::: "memory")

// ================= unified bf16 GEMM: out = A @ B^T over pre-converted tiles =====
// EPI==1 launches with gridDim.z = 2*BATCH: z<32 -> set1 (feat-a), z>=32 -> set2
template <int EPI, int BTRANS>
__global__ __launch_bounds__(256) void gemm_bf(
    const char* __restrict__ A1, const char* __restrict__ B1, float* __restrict__ o1,
    const int* __restrict__ cntM1, const int* __restrict__ cntN1, const int* __restrict__ idxM1,
    const char* __restrict__ A2, const char* __restrict__ B2, float* __restrict__ o2,
    const int* __restrict__ cntM2, const int* __restrict__ cntN2, const int* __restrict__ idxM2,
    const float* __restrict__ temp_ptr)
{
    extern __shared__ char sm[];
    const int tid = threadIdx.x;
    int bz = blockIdx.z;
    const bool second = (EPI == 1) && (bz >= BATCH);
    if (second) bz -= BATCH;
    const char* Abuf = second ? A2 : A1;
    const char* Bbuf = second ? B2 : B1;
    float* out       = second ? o2 : o1;
    const int* cntM  = second ? cntM2 : cntM1;
    const int* cntN  = second ? cntN2 : cntN1;
    const int* idxM  = second ? idxM2 : idxM1;

    const int cm = cntM[bz];
    const int mc = (cm + 127) & ~127;
    const int rowC = blockIdx.y * 128;
    if (rowC >= mc) return;
    const int colC = blockIdx.x * 128;
    int nstg, nb = 0;
    if (EPI == 0) {
        nb = cntN[bz];
        const int nbc = (nb + 127) & ~127;
        if (colC >= nbc) return;
        nstg = 32;
    } else {
        nstg = (cntN[bz] + 31) >> 5;
    }

    const char* gA = Abuf + ((size_t)bz << 22);
    const char* gB = Bbuf + ((size_t)bz << 22);

    const int lr = tid >> 1;
    const int cb = (tid & 1) * 64;
    const int rB = tid >> 3;
    const int oB = (tid & 7) * 64;
    const int ks0 = colC >> 5;
    const uint32_t smb = smem_u32(sm);

    #define ISSUE_STAGE(s) do { \
        const uint32_t _st = smb + ((s) % 3) * 32768; \
        const uint32_t _dA = _st + lr * 128 + cb; \
        const char* _pA = gA + (((size_t)(rowC + lr) * 32 + (s)) << 7) + cb; \
        cpa16(_dA,          _pA);      cpa16(_dA + 16,         _pA + 16); \
        cpa16(_dA + 32,     _pA + 32); cpa16(_dA + 48,         _pA + 48); \
        if (BTRANS) { \
            const uint32_t _dB = _st + 16384 + rB * 512 + oB; \
            const char* _pB = gB + (((size_t)((s) * 32 + rB) * 32 + ks0) << 7) + oB; \
            cpa16(_dB,      _pB);      cpa16(_dB + 16,     _pB + 16); \
            cpa16(_dB + 32, _pB + 32); cpa16(_dB + 48,     _pB + 48); \
        } else { \
            const uint32_t _dB = _st + 16384 + lr * 128 + cb; \
            const char* _pB = gB + (((size_t)(colC + lr) * 32 + (s)) << 7) + cb; \
            cpa16(_dB,      _pB);      cpa16(_dB + 16,     _pB + 16); \
            cpa16(_dB + 32, _pB + 32); cpa16(_dB + 48,     _pB + 48); \
        } \
    } while (0)

    float acc[2][8][4];
    #pragma unroll
    for (int i = 0; i < 2; i++)
        #pragma unroll
        for (int j = 0; j < 8; j++)
            #pragma unroll
            for (int k = 0; k < 4; k++) acc[i][j][k] = 0.f;

    const int wid = tid >> 5;
    const int l   = tid & 31;
    const int m0 = (wid & 3) * 32;
    const int n0 = (wid >> 2) * 64;
    const int lrA = l & 15;
    const int lcA = l >> 4;
    const int lrB = (l & 7) + ((l & 16) >> 1);
    const int lcB = (l >> 3) & 1;
    const int jof = (l & 7) + ((l & 8) ? 8 : 0);
    const int nof = (l & 16) ? 8 : 0;

    ISSUE_STAGE(0); CPA_COMMIT();
    if (nstg > 1) ISSUE_STAGE(1);
    CPA_COMMIT();

    for (int s = 0; s < nstg; ++s) {
        CPA_WAIT1();
        __syncthreads();
        if (s + 2 < nstg) ISSUE_STAGE(s + 2);
        CPA_COMMIT();

        const uint32_t sAb = smb + (s % 3) * 32768;
        const uint32_t sBb = sAb + 16384;
        #pragma unroll
        for (int kc = 0; kc < 4; kc += 2) {
            uint32_t a_hi[2][4], a_lo[2][4];
            #pragma unroll
            for (int mi = 0; mi < 2; ++mi) {
                const int r = m0 + mi * 16 + lrA;
                const int rx = r & 7;
                ldm_x4(a_hi[mi], sAb + r * 128 + (((kc     + lcA) ^ rx) * 16));
                ldm_x4(a_lo[mi], sAb + r * 128 + (((kc + 4 + lcA) ^ rx) * 16));
            }
            #pragma unroll
            for (int nh = 0; nh < 2; ++nh) {
                uint32_t b_hi[2][4], b_lo[2][4];
                #pragma unroll
                for (int nt = 0; nt < 2; ++nt) {
                    if (BTRANS) {
                        const int jrow = (kc >> 1) * 16 + jof;
                        const int nloc = n0 + nh * 32 + nt * 16 + nof;
                        const int slab = nloc >> 5;
                        const int ch   = (nloc >> 3) & 3;
                        const uint32_t base = sBb + jrow * 512 + slab * 128;
                        const int rx = jrow & 7;
                        ldm_x4_t(b_hi[nt], base + (((ch    ) ^ rx) * 16));
                        ldm_x4_t(b_lo[nt], base + (((ch + 4) ^ rx) * 16));
                    } else {
                        const int r = n0 + nh * 32 + nt * 16 + lrB;
                        const int rx = r & 7;
                        ldm_x4(b_hi[nt], sBb + r * 128 + (((kc     + lcB) ^ rx) * 16));
                        ldm_x4(b_lo[nt], sBb + r * 128 + (((kc + 4 + lcB) ^ rx) * 16));
                    }
                }
                // product-major ordering over 8 independent accumulators
                #pragma unroll
                for (int prod = 0; prod < 3; ++prod)
                    #pragma unroll
                    for (int mi = 0; mi < 2; ++mi)
                        #pragma unroll
                        for (int nt = 0; nt < 2; ++nt)
                            #pragma unroll
                            for (int p = 0; p < 2; ++p) {
                                const int j = nh * 4 + nt * 2 + p;
                                mma16816(acc[mi][j],
                                         (prod == 2) ? a_lo[mi] : a_hi[mi],
                                         (prod == 1) ? &b_lo[nt][p * 2] : &b_hi[nt][p * 2]);
                            }
            }
        }
    }
    __syncthreads();

    float* eb = (float*)sm;
    #pragma unroll
    for (int mi = 0; mi < 2; ++mi)
        #pragma unroll
        for (int j = 0; j < 8; ++j) {
            const int r0 = m0 + mi * 16 + (l >> 2);
            const int col = n0 + j * 8 + (l & 3) * 2;
            const int ch = col >> 2, fo = col & 3;
            *(float2*)(eb + r0 * 128 + (ch ^ (r0 & 7)) * 4 + fo) =
                make_float2(acc[mi][j][0], acc[mi][j][1]);
            const int r1 = r0 + 8;
            *(float2*)(eb + r1 * 128 + (ch ^ (r1 & 7)) * 4 + fo) =
                make_float2(acc[mi][j][2], acc[mi][j][3]);
        }
    __syncthreads();

    if (EPI == 0) {
        float* Cb = g_S + ((size_t)bz << 20) + (size_t)rowC * 1024 + colC;
        const float temp = *temp_ptr;
        const int c = tid & 31;
        #pragma unroll
        for (int p = 0; p < 16; ++p) {
            const int row = p * 8 + wid;
            float4 v = *(float4*)(eb + row * 128 + ((c ^ (row & 7)) * 4));
            const bool rv = (rowC + row) < cm;
            const int cbi = colC + c * 4;
            v.x = (rv && cbi + 0 < nb) ? v.x * temp : -10000.0f;
            v.y = (rv && cbi + 1 < nb) ? v.y * temp : -10000.0f;
            v.z = (rv && cbi + 2 < nb) ? v.z * temp : -10000.0f;
            v.w = (rv && cbi + 3 < nb) ? v.w * temp : -10000.0f;
            *(float4*)(Cb + (size_t)row * 1024 + c * 4) = v;
            *(float4*)(eb + row * 128 + ((c ^ (row & 7)) * 4)) = v;
            float m4 = fmaxf(fmaxf(v.x, v.y), fmaxf(v.z, v.w));
            #pragma unroll
            for (int off = 16; off > 0; off >>= 1)
                m4 = fmaxf(m4, __shfl_xor_sync(0xffffffffu, m4, off));
            float e = expf(v.x - m4) + expf(v.y - m4) + expf(v.z - m4) + expf(v.w - m4);
            #pragma unroll
            for (int off = 16; off > 0; off >>= 1)
                e += __shfl_xor_sync(0xffffffffu, e, off);
            if (c == 0) {
                g_rpm[(blockIdx.x * 32 + bz) * 1024 + rowC + row] = m4;
                g_rpl[(blockIdx.x * 32 + bz) * 1024 + rowC + row] = e;
            }
        }
        __syncthreads();
        float* cm2 = (float*)(sm + 65536);
        float* cl2 = cm2 + 128;
        const int col = tid & 127;
        const int half = tid >> 7;
        float m = -1e30f;
        #pragma unroll 4
        for (int r = half * 64; r < half * 64 + 64; ++r)
            m = fmaxf(m, eb[r * 128 + (((col >> 2) ^ (r & 7)) * 4) + (col & 3)]);
        float lsum = 0.f;
        #pragma unroll 4
        for (int r = half * 64; r < half * 64 + 64; ++r)
            lsum += expf(eb[r * 128 + (((col >> 2) ^ (r & 7)) * 4) + (col & 3)] - m);
        if (half == 1) { cm2[col] = m; cl2[col] = lsum; }
        __syncthreads();
        if (half == 0) {
            float pm = cm2[col], pl = cl2[col];
            float nm = fmaxf(m, pm);
            lsum = lsum * expf(m - nm) + pl * expf(pm - nm);
            g_cpm[(blockIdx.y * 32 + bz) * 1024 + colC + col] = nm;
            g_cpl[(blockIdx.y * 32 + bz) * 1024 + colC + col] = lsum;
        }
    } else {
        const int* im = idxM + bz * 1024;
        float* Ob = out + ((size_t)bz << 20);
        #pragma unroll
        for (int p = 0; p < 16; ++p) {
            const int idx = p * 256 + tid;
            const int row = idx >> 5;
            const int c   = idx & 31;
            const int gi = rowC + row;
            if (gi < cm) {
                float4 v = *(float4*)(eb + row * 128 + ((c ^ (row & 7)) * 4));
                *(float4*)(Ob + (size_t)im[gi] * 1024 + colC + c * 4) = v;
            }
        }
    }
    #undef ISSUE_STAGE
}

// ---------------- mask scan: per-batch valid index lists ----------------
__global__ __launch_bounds__(256) void mask_scan(const int* __restrict__ ma,
                                                 const int* __restrict__ mb)
{
    const int b = blockIdx.x;
    const int which = blockIdx.y;
    const int* m = (which ? mb : ma) + b * 1024;
    int* idx = (which ? g_idxb : g_idxa) + b * 1024;
    const int tid = threadIdx.x;
    int4 v = ((const int4*)m)[tid];
    const int c0 = (v.x != 0), c1 = (v.y != 0), c2 = (v.z != 0), c3 = (v.w != 0);
    int s0 = c0 + c1 + c2 + c3;
    __shared__ int ps[256];
    ps[tid] = s0; __syncthreads();
    for (int off = 1; off < 256; off <<= 1) {
        int t = (tid >= off) ? ps[tid - off] : 0;
        __syncthreads();
        ps[tid] += t;
        __syncthreads();
    }
    int p = ps[tid] - s0;
    if (c0) idx[p++] = tid * 4 + 0;
    if (c1) idx[p++] = tid * 4 + 1;
    if (c2) idx[p++] = tid * 4 + 2;
    if (c3) idx[p++] = tid * 4 + 3;
    if (tid == 255) (which ? g_nb : g_na)[b] = ps[255];
}

// ------- conv_km: gathered rows of a/b -> bf16 hi|lo pre-swizzled K-major -------
__global__ __launch_bounds__(256) void conv_km(const float* __restrict__ a,
                                               const float* __restrict__ bsrc)
{
    const int z = blockIdx.y;
    const float* in = (z < 32 ? a : bsrc) + ((size_t)(z & 31) << 20);
    char* out = (z < 32 ? g_aC : g_bC) + ((size_t)(z & 31) << 22);
    const int* idx = (z < 32 ? g_idxa : g_idxb) + (z & 31) * 1024;
    const int cnt = (z < 32 ? g_na : g_nb)[z & 31];
    const int nc = (cnt + 127) & ~127;
    const int lin = blockIdx.x * 256 + threadIdx.x;
    const int row = lin >> 5;
    if (row >= nc) return;
    char* dst = out + (size_t)lin * 128;
    const int rx = row & 7;
    if (row < cnt) {
        const int ks = lin & 31;
        const float4* src = (const float4*)(in + (size_t)idx[row] * 1024 + ks * 32);
        #pragma unroll
        for (int c = 0; c < 4; ++c) {
            float4 u = src[2 * c], v = src[2 * c + 1];
            float f[8] = {u.x, u.y, u.z, u.w, v.x, v.y, v.z, v.w};
            *(uint4*)(dst + (((c    ) ^ rx) * 16)) = pack8(f, false);
            *(uint4*)(dst + (((c + 4) ^ rx) * 16)) = pack8(f, true);
        }
    } else {
        #pragma unroll
        for (int pc = 0; pc < 8; ++pc)
            *(uint4*)(dst + pc * 16) = make_uint4(0, 0, 0, 0);
    }
}

// ---------------- column means (partials + combine, deterministic) ----------------
__global__ __launch_bounds__(256) void means_part(const float* __restrict__ a,
                                                  const float* __restrict__ bsrc)
{
    const int z = blockIdx.z;
    const float* src = (z < 32 ? a : bsrc) + ((size_t)(z & 31) << 20);
    const int h = blockIdx.x * 256 + threadIdx.x;
    const int s0 = blockIdx.y * 128;
    float sum = 0.f;
    #pragma unroll 4
    for (int s = 0; s < 128; ++s)
        sum += src[(size_t)(s0 + s) * 1024 + h];
    g_mp[((size_t)blockIdx.y * 64 + z) * 1024 + h] = sum;
}
__global__ __launch_bounds__(256) void means_comb()
{
    const int z = blockIdx.y;
    const int h = blockIdx.x * 256 + threadIdx.x;
    float sum = 0.f;
    #pragma unroll
    for (int q = 0; q < 8; ++q)
        sum += g_mp[((size_t)(q * 64 + z) << 10) + h];
    float* dst = (z < 32 ? g_amean : g_bmean) + (z & 31) * 1024;
    dst[h] = sum;
}

// ---------------- merged combine kernel for fused softmax partials ----------------
__global__ __launch_bounds__(256) void stats_comb()
{
    const int b = blockIdx.y;
    const int i = blockIdx.x * 256 + threadIdx.x;
    const int which = blockIdx.z;
    const int qn = ((which ? g_na[b] : g_nb[b]) + 127) >> 7;
    const float* pm_arr = which ? g_cpm : g_rpm;
    const float* pl_arr = which ? g_cpl : g_rpl;
    float m = -1e30f, lsum = 0.f;
    for (int q = 0; q < qn; ++q) {
        float pm = pm_arr[(q * 32 + b) * 1024 + i];
        float pl = pl_arr[(q * 32 + b) * 1024 + i];
        float nm = fmaxf(m, pm);
        lsum = lsum * expf(m - nm) + pl * expf(pm - nm);
        m = nm;
    }
    if (which) {
        g_cmax[b * 1024 + i] = m;
        g_cinv[b * 1024 + i] = 1.0f / lsum;
    } else {
        g_rmax[b * 1024 + i] = m;
        g_rinv[b * 1024 + i] = 1.0f / lsum;
    }
}

// ------- probabilities: write Pb and PaT directly as bf16 hi|lo pre-swizzled -------
__global__ __launch_bounds__(256) void probs_c()
{
    const int b  = blockIdx.z;
    const int nac = (g_na[b] + 127) & ~127;
    const int nbc = (g_nb[b] + 127) & ~127;
    const int t0 = blockIdx.x * 32;
    const int s0 = blockIdx.y * 32;
    if (s0 >= nac || t0 >= nbc) return;
    const int tx = threadIdx.x & 31;
    const int ty = threadIdx.x >> 5;
    __shared__ float pb[32][33];
    __shared__ float pa[32][33];
    const float* Sb = g_S + ((size_t)b << 20);
    const float cm = g_cmax[b * 1024 + t0 + tx];
    const float ci = g_cinv[b * 1024 + t0 + tx];
    #pragma unroll
    for (int r = 0; r < 4; r++) {
        const int s = s0 + ty + r * 8;
        float x = Sb[(size_t)s * 1024 + t0 + tx];
        pb[ty + r * 8][tx] = expf(x - g_rmax[b * 1024 + s]) * g_rinv[b * 1024 + s];
        pa[tx][ty + r * 8] = expf(x - cm) * ci;
    }
    __syncthreads();
    const int row = threadIdx.x >> 3;
    const int c   = threadIdx.x & 7;
    const bool lo = (c >= 4);
    {
        const int s = s0 + row;
        uint4 w = pack8(&pb[row][(c & 3) * 8], lo);
        *(uint4*)(g_PbC + ((size_t)b << 22) + (((size_t)s * 32 + (t0 >> 5)) << 7)
                  + ((c ^ (s & 7)) * 16)) = w;
    }
    {
        const int t = t0 + row;
        uint4 w = pack8(&pa[row][(c & 3) * 8], lo);
        *(uint4*)(g_PaTC + ((size_t)b << 22) + (((size_t)t * 32 + (s0 >> 5)) << 7)
                  + ((c ^ (t & 7)) * 16)) = w;
    }
}

// ------- fill invalid output rows with mean of the opposite tensor ---------
__global__ __launch_bounds__(256) void fill_invalid(const int* __restrict__ mask,
                                                    const float* __restrict__ meansum,
                                                    float* __restrict__ out)
{
    const int b = blockIdx.y;
    const int s = blockIdx.x;
    if (mask[b * 1024 + s]) return;
    const float4 v = ((const float4*)(meansum + b * 1024))[threadIdx.x];
    const float inv = 1.0f / 1024.0f;
    ((float4*)(out + ((size_t)b << 20) + (size_t)s * 1024))[threadIdx.x] =
        make_float4(v.x * inv, v.y * inv, v.z * inv, v.w * inv);
}

// ---------------- launch: two-stream overlap, merged feature GEMM --------------
extern "C" void kernel_launch(void* const* d_in, const int* in_sizes, int n_in,
                              void* d_out, int out_size)
{
    const float* a    = (const float*)d_in[0];
    const float* b    = (const float*)d_in[1];
    const int*   ma   = (const int*)d_in[2];
    const int*   mb   = (const int*)d_in[3];
    const float* temp = (const float*)d_in[4];

    float* fa = (float*)d_out;
    float* fb = fa + (size_t)BATCH * L * HD;

    float* pS;   cudaGetSymbolAddress((void**)&pS,   g_S);
    char* paC;   cudaGetSymbolAddress((void**)&paC,  g_aC);
    char* pbC;   cudaGetSymbolAddress((void**)&pbC,  g_bC);
    char* pPbC;  cudaGetSymbolAddress((void**)&pPbC, g_PbC);
    char* pPaTC; cudaGetSymbolAddress((void**)&pPaTC, g_PaTC);
    float* pam;  cudaGetSymbolAddress((void**)&pam,  g_amean);
    float* pbm;  cudaGetSymbolAddress((void**)&pbm,  g_bmean);
    int* pna;    cudaGetSymbolAddress((void**)&pna,  g_na);
    int* pnb;    cudaGetSymbolAddress((void**)&pnb,  g_nb);
    int* pia;    cudaGetSymbolAddress((void**)&pia,  g_idxa);
    int* pib;    cudaGetSymbolAddress((void**)&pib,  g_idxb);

    static cudaStream_t s2 = nullptr;
    static cudaEvent_t evConv = nullptr, evJoin = nullptr;
    static bool inited = false;
    if (!inited) {
        cudaStreamCreateWithFlags(&s2, cudaStreamNonBlocking);
        cudaEventCreateWithFlags(&evConv, cudaEventDisableTiming);
        cudaEventCreateWithFlags(&evJoin, cudaEventDisableTiming);
        const int SMEM = 98304;
        cudaFuncSetAttribute(gemm_bf<0,0>, cudaFuncAttributeMaxDynamicSharedMemorySize, SMEM);
        cudaFuncSetAttribute(gemm_bf<1,1>, cudaFuncAttributeMaxDynamicSharedMemorySize, SMEM);
        inited = true;
    }
    const int SMEM = 98304;

    dim3 blk(256);

    // ---- main chain: mask scan + conversion get the DRAM to themselves ----
    mask_scan<<<dim3(32, 2), blk>>>(ma, mb);
    conv_km<<<dim3(128, 64), blk>>>(a, b);
    cudaEventRecord(evConv, 0);

    gemm_bf<0,0><<<dim3(8, 8, 32), blk, SMEM>>>(
        paC, pbC, pS, pna, pnb, nullptr,
        nullptr, nullptr, nullptr, nullptr, nullptr, nullptr, temp);

    // ---- side chain on s2 under the scores GEMM ----
    cudaStreamWaitEvent(s2, evConv, 0);
    means_part<<<dim3(4, 8, 64), blk, 0, s2>>>(a, b);
    means_comb<<<dim3(4, 64), blk, 0, s2>>>();
    fill_invalid<<<dim3(1024, 32), blk, 0, s2>>>(ma, pbm, fa);
    fill_invalid<<<dim3(1024, 32), blk, 0, s2>>>(mb, pam, fb);

    // ---- main chain continues ----
    stats_comb<<<dim3(4, 32, 2), blk>>>();
    probs_c<<<dim3(32, 32, 32), blk>>>();

    // merged feature GEMM: z = 0..31 -> feat-a, z = 32..63 -> feat-b
    gemm_bf<1,1><<<dim3(8, 8, 64), blk, SMEM>>>(
        pPbC, pbC, fa, pna, pnb, pia,
        pPaTC, paC, fb, pnb, pna, pib, nullptr);

    cudaEventRecord(evJoin, s2);
    cudaStreamWaitEvent(0, evJoin, 0);
}